// round 4
// baseline (speedup 1.0000x reference)
#include <cuda_runtime.h>
#include <cstdint>

// ============================================================================
// LSTMCell on GB300 via mma.sync TF32 (tcgen05 is PTX-target-gated off: the
// harness compiles at virtual target sm_103, which rejects all tcgen05).
//   gates = [X|H][8192,2048] @ W[2048,4096] + b  -> LSTM elementwise
// Single-pass TF32 (rel err ~2-4e-4 < 1e-3). Converters pre-arrange operands
// in MMA-fragment order in gmem so the GEMM does contiguous cp.async stage
// loads and conflict-free LDS.128 fragment fetches.
// ============================================================================

static constexpr int DIN  = 1024;
static constexpr int DOUT = 1024;
static constexpr int BT   = 8192;
static constexpr int KD   = 2048;   // DIN + DOUT
static constexpr int NG   = 4096;   // 4 gates * DOUT

// Scratch (module-load allocation; allowed)
__device__ float g_Xf[(size_t)BT * KD];    // A, fragment-ordered tf32
__device__ float g_Wf[(size_t)NG * KD];    // B, fragment-ordered tf32 (swizzled)
__device__ float g_gates[(size_t)BT * NG]; // GEMM output (pre-activation)

__device__ __forceinline__ unsigned f2tf(float v) {
    unsigned r;
    asm("cvt.rna.tf32.f32 %0, %1;" : "=r"(r) : "f"(v));
    return r;
}

// ---------------------------------------------------------------------------
// conv_x: X = [x|h] -> g_Xf in A-fragment order.
// Layout: f4 index o -> (mt = o>>13, ks = (o>>5)&255, lane = o&31).
// Lane's 4 regs = A frag of m16k8 tile (mt, ks):
//   a0=(g,c) a1=(g+8,c) a2=(g,c+4) a3=(g+8,c+4); g=lane>>2, c=lane&3.
// ---------------------------------------------------------------------------
__global__ void conv_x(const float* __restrict__ x, const float* __restrict__ h) {
    unsigned o = blockIdx.x * blockDim.x + threadIdx.x;  // 4M f4 total
    unsigned lane = o & 31u, ks = (o >> 5) & 255u, mt = o >> 13;
    int g = lane >> 2, c = lane & 3;
    int kb = ks * 8;
    int m0 = mt * 16 + g;
    const float* p = (kb < DIN) ? (x + (size_t)m0 * DIN + kb + c)
                                : (h + (size_t)m0 * DOUT + (kb - DIN) + c);
    float v0 = p[0], v2 = p[4];
    p += 8 * 1024;  // DIN == DOUT == 1024
    float v1 = p[0], v3 = p[4];
    uint4 r = make_uint4(f2tf(v0), f2tf(v1), f2tf(v2), f2tf(v3));
    ((uint4*)g_Xf)[o] = r;
}

// ---------------------------------------------------------------------------
// conv_w: W[k,1024] per gate -> g_Wf in B-fragment order (transposed, K-major).
// Layout float index: ((nt*64 + ksc)*32 + lane)*8 + jp*4 + (ksl&1)*2 + {0,1}
//   nt = global n-tile (8 cols), ksc = k chunk of 4 ksteps, jp = (ksl>>1) ^ ((lane>>2)&1)
// Lane's b0,b1 for kstep ksl: (k=c, n=g), (k=c+4, n=g).
// ---------------------------------------------------------------------------
__global__ void conv_w(const float* __restrict__ WI, const float* __restrict__ WF,
                       const float* __restrict__ WG, const float* __restrict__ WO) {
    __shared__ float tileT[32][33];  // [n_local][k_local]
    int tx = threadIdx.x, ty = threadIdx.y;  // 32 x 8
    int bx = blockIdx.x;                     // 0..127
    int gate = bx >> 5;
    int n0 = (bx & 31) * 32;
    int k0 = blockIdx.y * 32;
    const float* W = (gate == 0) ? WI : (gate == 1) ? WF : (gate == 2) ? WG : WO;
#pragma unroll
    for (int i = 0; i < 4; i++)
        tileT[tx][ty + 8 * i] = W[(size_t)(k0 + ty + 8 * i) * DOUT + n0 + tx];
    __syncthreads();
    int t = ty * 32 + tx;
#pragma unroll
    for (int pp = 0; pp < 2; ++pp) {
        int p = t + pp * 256;            // 512 float2-pairs per block
        int ksl = p & 3, lane = (p >> 2) & 31, lnt = p >> 7;
        int g = lane >> 2, c = lane & 3;
        int nl = lnt * 8 + g, kl = ksl * 8 + c;
        float b0 = tileT[nl][kl], b1 = tileT[nl][kl + 4];
        int jp = (ksl >> 1) ^ ((lane >> 2) & 1);
        size_t nt = (size_t)gate * 128 + (n0 >> 3) + lnt;
        size_t ksc = (size_t)(k0 >> 5);
        float* dst = g_Wf + ((nt * 64 + ksc) * 32 + lane) * 8 + jp * 4 + (ksl & 1) * 2;
        float2 w;
        w.x = __uint_as_float(f2tf(b0));
        w.y = __uint_as_float(f2tf(b1));
        *(float2*)dst = w;
    }
}

// ---------------------------------------------------------------------------
// TF32 GEMM: 128x128x32 tiles, 256 threads, 2-stage cp.async double buffer.
// Warp tile 32x64 (2 m-tiles x 8 n-tiles), mma.m16n8k8.
// ---------------------------------------------------------------------------
static constexpr int ITERS = KD / 32;  // 64

__device__ __forceinline__ void cpa16(unsigned saddr, const void* g) {
    size_t gp = __cvta_generic_to_global(g);
    asm volatile("cp.async.cg.shared.global [%0], [%1], 16;" :: "r"(saddr), "l"(gp) : "memory");
}

__device__ __forceinline__ void mma_tf32(float* d, uint4 a, unsigned b0, unsigned b1) {
    asm volatile(
        "mma.sync.aligned.m16n8k8.row.col.f32.tf32.tf32.f32 "
        "{%0,%1,%2,%3}, {%4,%5,%6,%7}, {%8,%9}, {%0,%1,%2,%3};"
        : "+f"(d[0]), "+f"(d[1]), "+f"(d[2]), "+f"(d[3])
        : "r"(a.x), "r"(a.y), "r"(a.z), "r"(a.w), "r"(b0), "r"(b1));
}

__global__ void __launch_bounds__(256, 2)
gemm_tf32(float* __restrict__ gates) {
    extern __shared__ float smem[];  // 2 stages x (A 4096 + B 4096) floats = 64KB
    unsigned sbase = (unsigned)__cvta_generic_to_shared(smem);
    int tid = threadIdx.x;
    int bx = blockIdx.x;  // n block 0..31
    int by = blockIdx.y;  // m block 0..63
    int mt0 = by * 8, nt0 = bx * 16;
    int warp = tid >> 5, lane = tid & 31;
    int wm = warp & 3, wn = warp >> 2;

    float acc[2][8][4];
#pragma unroll
    for (int mi = 0; mi < 2; ++mi)
#pragma unroll
        for (int ni = 0; ni < 8; ++ni)
#pragma unroll
            for (int e = 0; e < 4; ++e) acc[mi][ni][e] = 0.f;

    const uint4* Xf4 = (const uint4*)g_Xf;
    const uint4* Wf4 = (const uint4*)g_Wf;

    auto load_stage = [&](int it, int s) {
        unsigned stA = sbase + (unsigned)s * 32768u;
        unsigned stB = stA + 16384u;
#pragma unroll
        for (int i = 0; i < 4; ++i) {  // A: 1024 f4
            int u = tid + i * 256;
            int mtl = u >> 7, off = u & 127;
            cpa16(stA + (unsigned)u * 16u,
                  Xf4 + ((size_t)(mt0 + mtl) * 256 + it * 4) * 32 + off);
        }
#pragma unroll
        for (int i = 0; i < 4; ++i) {  // B: 1024 f4
            int u = tid + i * 256;
            int ntl = u >> 6, off = u & 63;
            cpa16(stB + (unsigned)u * 16u,
                  Wf4 + ((size_t)(nt0 + ntl) * 64 + it) * 64 + off);
        }
    };

    load_stage(0, 0);
    asm volatile("cp.async.commit_group;" ::: "memory");

    for (int it = 0; it < ITERS; ++it) {
        int s = it & 1;
        if (it + 1 < ITERS) {
            load_stage(it + 1, s ^ 1);
            asm volatile("cp.async.commit_group;" ::: "memory");
            asm volatile("cp.async.wait_group 1;" ::: "memory");
        } else {
            asm volatile("cp.async.wait_group 0;" ::: "memory");
        }
        __syncthreads();

        const float* stA = smem + s * 8192;
        const float* stB = stA + 4096;
        int bsw = (lane >> 2) & 1;
#pragma unroll
        for (int j = 0; j < 2; ++j) {  // kstep pairs
            uint4 a[2][2];
#pragma unroll
            for (int mi = 0; mi < 2; ++mi)
#pragma unroll
                for (int kk = 0; kk < 2; ++kk)
                    a[mi][kk] = *(const uint4*)(stA +
                        ((wm * 2 + mi) * 4 + (j * 2 + kk)) * 128 + lane * 4);
            int jp = j ^ bsw;
#pragma unroll
            for (int ni = 0; ni < 8; ++ni) {
                uint4 b = *(const uint4*)(stB + ((wn * 8 + ni) * 32 + lane) * 8 + jp * 4);
#pragma unroll
                for (int mi = 0; mi < 2; ++mi) {
                    mma_tf32(acc[mi][ni], a[mi][0], b.x, b.y);
                    mma_tf32(acc[mi][ni], a[mi][1], b.z, b.w);
                }
            }
        }
        __syncthreads();
    }

    // Epilogue: write pre-activations to g_gates
#pragma unroll
    for (int mi = 0; mi < 2; ++mi) {
#pragma unroll
        for (int ni = 0; ni < 8; ++ni) {
            int m = by * 128 + wm * 32 + mi * 16 + (lane >> 2);
            int n = bx * 128 + wn * 64 + ni * 8 + (lane & 3) * 2;
            float2 lo = make_float2(acc[mi][ni][0], acc[mi][ni][1]);
            float2 hi = make_float2(acc[mi][ni][2], acc[mi][ni][3]);
            *(float2*)&gates[(size_t)m * NG + n] = lo;
            *(float2*)&gates[(size_t)(m + 8) * NG + n] = hi;
        }
    }
}

// ---------------------------------------------------------------------------
// Elementwise LSTM: read 4 gate pre-activations + biases + c, write h and C.
// ---------------------------------------------------------------------------
__device__ __forceinline__ float sigm(float x) { return 1.f / (1.f + __expf(-x)); }
__device__ __forceinline__ float tanhx(float x) { return 2.f / (1.f + __expf(-2.f * x)) - 1.f; }

__global__ void lstm_elem(const float* __restrict__ c,
                          const float* __restrict__ bI, const float* __restrict__ bF,
                          const float* __restrict__ bG, const float* __restrict__ bO,
                          float* __restrict__ out) {
    unsigned t = blockIdx.x * blockDim.x + threadIdx.x;  // 2M
    int m = t >> 8;
    int nf = (t & 255) * 4;
    const float* gr = g_gates + (size_t)m * NG;
    float4 gi = *(const float4*)(gr + nf);
    float4 gf = *(const float4*)(gr + 1024 + nf);
    float4 gg = *(const float4*)(gr + 2048 + nf);
    float4 go = *(const float4*)(gr + 3072 + nf);
    float4 vbi = *(const float4*)(bI + nf);
    float4 vbf = *(const float4*)(bF + nf);
    float4 vbg = *(const float4*)(bG + nf);
    float4 vbo = *(const float4*)(bO + nf);
    float4 cv = *(const float4*)(c + (size_t)m * DOUT + nf);

    float iv[4] = {gi.x + vbi.x, gi.y + vbi.y, gi.z + vbi.z, gi.w + vbi.w};
    float fv[4] = {gf.x + vbf.x, gf.y + vbf.y, gf.z + vbf.z, gf.w + vbf.w};
    float gv[4] = {gg.x + vbg.x, gg.y + vbg.y, gg.z + vbg.z, gg.w + vbg.w};
    float ov[4] = {go.x + vbo.x, go.y + vbo.y, go.z + vbo.z, go.w + vbo.w};
    float cc[4] = {cv.x, cv.y, cv.z, cv.w};

    float hv[4], Cv[4];
#pragma unroll
    for (int e = 0; e < 4; ++e) {
        float I = sigm(iv[e]), F = sigm(fv[e]), G = tanhx(gv[e]), O = sigm(ov[e]);
        float C = F * cc[e] + I * G;
        Cv[e] = C;
        hv[e] = O * tanhx(C);
    }
    float* hp = out + (size_t)m * DOUT + nf;
    float* cp = out + (size_t)BT * DOUT + (size_t)m * DOUT + nf;
    *(float4*)hp = make_float4(hv[0], hv[1], hv[2], hv[3]);
    *(float4*)cp = make_float4(Cv[0], Cv[1], Cv[2], Cv[3]);
}

// ---------------------------------------------------------------------------
// Launch
// ---------------------------------------------------------------------------
extern "C" void kernel_launch(void* const* d_in, const int* in_sizes, int n_in,
                              void* d_out, int out_size) {
    const float* x  = (const float*)d_in[0];
    const float* h  = (const float*)d_in[1];
    const float* c  = (const float*)d_in[2];
    const float* WI = (const float*)d_in[3];
    const float* bI = (const float*)d_in[4];
    const float* WF = (const float*)d_in[5];
    const float* bF = (const float*)d_in[6];
    const float* WG = (const float*)d_in[7];
    const float* bG = (const float*)d_in[8];
    const float* WO = (const float*)d_in[9];
    const float* bO = (const float*)d_in[10];
    float* out = (float*)d_out;

    conv_x<<<(BT * KD / 4) / 256, 256>>>(x, h);
    conv_w<<<dim3(128, 64), dim3(32, 8)>>>(WI, WF, WG, WO);

    float* gates;
    cudaGetSymbolAddress((void**)&gates, g_gates);
    cudaFuncSetAttribute(gemm_tf32, cudaFuncAttributeMaxDynamicSharedMemorySize, 65536);
    gemm_tf32<<<dim3(32, 64), 256, 65536>>>(gates);

    lstm_elem<<<(BT * DOUT / 4) / 256, 256>>>(c, bI, bF, bG, bO, out);
}